// round 5
// baseline (speedup 1.0000x reference)
#include <cuda_runtime.h>
#include <cuda_bf16.h>
#include <cstdint>

// Real spherical harmonics up to L=20 -> 441 cols/point, N=500k, fp32 out.
// 882 MB of output => HBM-write-bound.
//
// Round-5 design (= round 3 shape, made persistent):
//  - TILE=32 points, 128 threads: 4 threads/point split by m mod 4.
//  - Single 56448 B smem buffer per CTA -> 4 CTAs/SM = 16 warps/SM
//    (round 4 showed 2 CTAs/SM with double buffering loses: compute
//    parallelism matters more than per-CTA pipeline depth here).
//  * PERSISTENT: grid = 4 CTAs/SM, each loops over tiles. Removes ~26
//    wave transitions and their store-drain tails + CTA launch/retire.
//  * Coord LDGs for the next tile issued BEFORE the drain-wait, so the
//    ~600cyc load latency overlaps the previous tile's TMA drain.
//  - All recurrence coefficients + norms are compile-time immediates.
//  - Scatter STS (stride 441 words, odd => bank-conflict-free).
//  - Tile -> GMEM via one 1D cp.async.bulk store per tile; buffer reuse
//    gated by cp.async.bulk.wait_group 0 at loop top.

#define SH_L 20
#define SH_K 441
#define TILE 32
#define THREADS 128
#define TILE_BYTES (TILE * SH_K * 4)          // 56448
#define SMEM_BYTES TILE_BYTES                 // 4 CTAs/SM

// ---------- compile-time math ----------
__host__ __device__ constexpr double kPI_c() { return 3.141592653589793238462643383279502884; }

__host__ __device__ constexpr double csqrt(double x) {
    double g = (x > 1.0) ? x : 1.0;
    for (int i = 0; i < 200; ++i) g = 0.5 * (g + x / g);
    return g;
}

__host__ __device__ constexpr double inv_ratio(int l, int m) {
    double p = 1.0;
    for (int k = l - m + 1; k <= l + m; ++k) p *= (double)k;
    return p;
}

template <int L_, int M>
__host__ __device__ constexpr float nf_val() {
    double norm = csqrt((2.0 * L_ + 1.0) / (4.0 * kPI_c()) / inv_ratio(L_, M));
    return (float)(M > 0 ? norm * csqrt(2.0) : norm);
}

// ---------- store helpers ----------
template <int M, int L_>
__device__ __forceinline__ void storepair(float* __restrict__ row, float b,
                                          float cm, float sm) {
    if constexpr (M == 0) {
        row[L_ * (L_ + 1)] = b;
    } else {
        row[L_ * (L_ + 1) + M] = b * cm;
        row[L_ * (L_ + 1) - M] = b * sm;
    }
}

// ---------- l recursion for fixed m ----------
template <int M, int L_>
__device__ __forceinline__ void lstep(float* __restrict__ row, float ct,
                                      float cm, float sm, float p1, float p2) {
    constexpr float A = (float)((double)(2 * L_ - 1) / (double)(L_ - M));
    constexpr float B = (float)(-(double)(L_ + M - 1) / (double)(L_ - M));
    const float pv = fmaf(A * ct, p1, B * p2);
    constexpr float NF = nf_val<L_, M>();
    storepair<M, L_>(row, NF * pv, cm, sm);
    if constexpr (L_ < SH_L) lstep<M, L_ + 1>(row, ct, cm, sm, pv, p1);
}

// ---------- m chain: one residue class, m += 4 ----------
template <int M>
__device__ __forceinline__ void mchain(float* __restrict__ row, float ct,
                                       float st4, float c4, float s4,
                                       float pmm, float cm, float sm) {
    constexpr float NF0 = nf_val<M, M>();
    storepair<M, M>(row, NF0 * pmm, cm, sm);
    if constexpr (M < SH_L) {
        constexpr float C1 = (float)(2 * M + 1);
        const float p1 = (C1 * ct) * pmm;
        constexpr float NF1 = nf_val<M + 1, M>();
        storepair<M, M + 1>(row, NF1 * p1, cm, sm);
        if constexpr (M + 2 <= SH_L) lstep<M, M + 2>(row, ct, cm, sm, p1, pmm);
    }
    if constexpr (M + 4 <= SH_L) {
        constexpr float F = (float)((double)(2 * M + 1) * (2 * M + 3) *
                                    (2 * M + 5) * (2 * M + 7));
        const float pmm2 = (pmm * F) * st4;
        const float cn = fmaf(cm, c4, -(sm * s4));
        const float sn = fmaf(sm, c4, cm * s4);
        mchain<M + 4>(row, ct, st4, c4, s4, pmm2, cn, sn);
    }
}

__device__ __forceinline__ uint32_t smem_u32(const void* p) {
    uint32_t a;
    asm("{ .reg .u64 t; cvta.to.shared.u64 t, %1; cvt.u32.u64 %0, t; }"
        : "=r"(a) : "l"(p));
    return a;
}

// ---------- per-point compute from preloaded coords ----------
__device__ __forceinline__ void compute_point(float x, float y, float z,
                                              float* __restrict__ row, int w)
{
    const float r = sqrtf(x * x + y * y + z * z);
    float ct = z / r;
    ct = fminf(1.0f, fmaxf(-1.0f, ct));
    const float st = sqrtf(fmaxf(1.0f - ct * ct, 0.0f));
    const float st2 = st * st;
    const float st4 = st2 * st2;

    const float rho2 = x * x + y * y;
    float c1, s1;
    if (rho2 > 0.0f) {
        const float ir = rsqrtf(rho2);
        c1 = x * ir;
        s1 = y * ir;
    } else {
        c1 = 1.0f;
        s1 = 0.0f;
    }
    const float c2 = fmaf(c1, c1, -(s1 * s1));
    const float s2 = 2.0f * c1 * s1;
    const float c3 = fmaf(c2, c1, -(s2 * s1));
    const float s3 = fmaf(s2, c1, c2 * s1);
    const float c4 = fmaf(c2, c2, -(s2 * s2));
    const float s4 = 2.0f * c2 * s2;

    if (w == 0) {
        mchain<0>(row, ct, st4, c4, s4, 1.0f, 1.0f, 0.0f);
    } else if (w == 1) {
        mchain<1>(row, ct, st4, c4, s4, -st, c1, s1);
    } else if (w == 2) {
        const float pmm = (3.0f * st) * st;                 // P_2^2
        mchain<2>(row, ct, st4, c4, s4, pmm, c2, s2);
    } else {
        const float pmm = ((-15.0f * st) * st) * st;        // P_3^3
        mchain<3>(row, ct, st4, c4, s4, pmm, c3, s3);
    }
}

// ---------- kernel ----------
__global__ void __launch_bounds__(THREADS, 4)
sph_harm_kernel(const float* __restrict__ coords, float* __restrict__ out,
                int n, int ntiles)
{
    extern __shared__ float sh[];           // one tile buffer
    const int t = threadIdx.x;
    const int lane = t & 31;                // point within tile
    const int w = t >> 5;                   // m residue (0..3)
    float* row = sh + lane * SH_K;

    for (int tile = blockIdx.x; tile < ntiles; tile += gridDim.x) {
        const int base = tile * TILE;
        const int p = base + lane;
        const bool valid = (p < n);

        // issue coord loads BEFORE the drain-wait: LDG latency overlaps
        // the previous tile's TMA store drain
        float x = 0.0f, y = 0.0f, z = 0.0f;
        if (valid) {
            x = coords[3 * p + 0];
            y = coords[3 * p + 1];
            z = coords[3 * p + 2];
        }

        // gate buffer reuse on previous store having fully drained
        if (t == 0) {
            asm volatile("cp.async.bulk.wait_group 0;" ::: "memory");
        }
        __syncthreads();

        if (valid) compute_point(x, y, z, row, w);

        asm volatile("fence.proxy.async.shared::cta;" ::: "memory");
        __syncthreads();

        const int npts = min(TILE, n - base);
        float* gbase = out + (size_t)base * SH_K;

        if (npts == TILE) {
            if (t == 0) {
                const uint32_t saddr = smem_u32(sh);
                asm volatile(
                    "cp.async.bulk.global.shared::cta.bulk_group [%0], [%1], %2;"
                    :: "l"(gbase), "r"(saddr), "r"((uint32_t)TILE_BYTES)
                    : "memory");
                asm volatile("cp.async.bulk.commit_group;" ::: "memory");
            }
        } else if (npts > 0) {
            // partial tail tile: scalar coalesced fallback
            const int total = npts * SH_K;
            for (int i = t; i < total; i += THREADS) {
                gbase[i] = sh[i];
            }
            __syncthreads();
        }
    }

    // drain outstanding store before exit (smem must stay valid)
    if (t == 0) {
        asm volatile("cp.async.bulk.wait_group 0;" ::: "memory");
    }
}

extern "C" void kernel_launch(void* const* d_in, const int* in_sizes, int n_in,
                              void* d_out, int out_size) {
    const float* coords = (const float*)d_in[0];
    float* out = (float*)d_out;
    const int n = in_sizes[0] / 3;
    const int ntiles = (n + TILE - 1) / TILE;

    cudaFuncSetAttribute(sph_harm_kernel,
                         cudaFuncAttributeMaxDynamicSharedMemorySize, SMEM_BYTES);
    cudaFuncSetAttribute(sph_harm_kernel,
                         cudaFuncAttributePreferredSharedMemoryCarveout, 100);

    int dev = 0, nsm = 148;
    cudaGetDevice(&dev);
    cudaDeviceGetAttribute(&nsm, cudaDevAttrMultiProcessorCount, dev);
    int blocks = 4 * nsm;
    if (blocks > ntiles) blocks = ntiles;

    sph_harm_kernel<<<blocks, THREADS, SMEM_BYTES>>>(coords, out, n, ntiles);
}

// round 6
// speedup vs baseline: 1.1777x; 1.1777x over previous
#include <cuda_runtime.h>
#include <cuda_bf16.h>
#include <cstdint>

// Real spherical harmonics up to L=20 -> 441 cols/point, N=500k, fp32 out.
// 882 MB of output => HBM-write-bound.
//
// Round-6 = round-3 shape (best so far: 126.5us, DRAM 82.7%) + ONE change:
//  * cp.async.bulk.wait_group.READ instead of full wait_group: the CTA only
//    needs smem to remain valid until the TMA engine has READ the tile, not
//    until the GMEM writes land. CTA slots recycle ~1-2us sooner; fresh
//    compute backfills the SM and keeps the store queue full.
//  - TILE=32 points/CTA, 128 threads: 4 threads/point split by m mod 4.
//  - Non-persistent grid (15625 CTAs): retirement-staggered scheduling beat
//    both persistent variants (r4: 147us, r5: 149us) by keeping store
//    traffic phase-desynchronized across the 4 CTA slots per SM.
//  - All recurrence coefficients + norms are compile-time immediates (no LDC).
//  - Scatter STS (stride 441 words, odd => bank-conflict-free).
//  - smem 56448 B -> 4 CTAs/SM = 16 warps/SM.

#define SH_L 20
#define SH_K 441
#define TILE 32
#define THREADS 128
#define SMEM_BYTES (TILE * SH_K * 4)   // 56448

// ---------- compile-time math ----------
__host__ __device__ constexpr double kPI_c() { return 3.141592653589793238462643383279502884; }

__host__ __device__ constexpr double csqrt(double x) {
    double g = (x > 1.0) ? x : 1.0;
    for (int i = 0; i < 200; ++i) g = 0.5 * (g + x / g);
    return g;
}

__host__ __device__ constexpr double inv_ratio(int l, int m) {
    double p = 1.0;
    for (int k = l - m + 1; k <= l + m; ++k) p *= (double)k;
    return p;
}

template <int L_, int M>
__host__ __device__ constexpr float nf_val() {
    double norm = csqrt((2.0 * L_ + 1.0) / (4.0 * kPI_c()) / inv_ratio(L_, M));
    return (float)(M > 0 ? norm * csqrt(2.0) : norm);
}

// ---------- store helpers ----------
template <int M, int L_>
__device__ __forceinline__ void storepair(float* __restrict__ row, float b,
                                          float cm, float sm) {
    if constexpr (M == 0) {
        row[L_ * (L_ + 1)] = b;
    } else {
        row[L_ * (L_ + 1) + M] = b * cm;
        row[L_ * (L_ + 1) - M] = b * sm;
    }
}

// ---------- l recursion for fixed m ----------
template <int M, int L_>
__device__ __forceinline__ void lstep(float* __restrict__ row, float ct,
                                      float cm, float sm, float p1, float p2) {
    constexpr float A = (float)((double)(2 * L_ - 1) / (double)(L_ - M));
    constexpr float B = (float)(-(double)(L_ + M - 1) / (double)(L_ - M));
    const float pv = fmaf(A * ct, p1, B * p2);
    constexpr float NF = nf_val<L_, M>();
    storepair<M, L_>(row, NF * pv, cm, sm);
    if constexpr (L_ < SH_L) lstep<M, L_ + 1>(row, ct, cm, sm, pv, p1);
}

// ---------- m chain: one residue class, m += 4 ----------
template <int M>
__device__ __forceinline__ void mchain(float* __restrict__ row, float ct,
                                       float st4, float c4, float s4,
                                       float pmm, float cm, float sm) {
    constexpr float NF0 = nf_val<M, M>();
    storepair<M, M>(row, NF0 * pmm, cm, sm);
    if constexpr (M < SH_L) {
        constexpr float C1 = (float)(2 * M + 1);
        const float p1 = (C1 * ct) * pmm;
        constexpr float NF1 = nf_val<M + 1, M>();
        storepair<M, M + 1>(row, NF1 * p1, cm, sm);
        if constexpr (M + 2 <= SH_L) lstep<M, M + 2>(row, ct, cm, sm, p1, pmm);
    }
    if constexpr (M + 4 <= SH_L) {
        constexpr float F = (float)((double)(2 * M + 1) * (2 * M + 3) *
                                    (2 * M + 5) * (2 * M + 7));
        const float pmm2 = (pmm * F) * st4;
        const float cn = fmaf(cm, c4, -(sm * s4));
        const float sn = fmaf(sm, c4, cm * s4);
        mchain<M + 4>(row, ct, st4, c4, s4, pmm2, cn, sn);
    }
}

__device__ __forceinline__ uint32_t smem_u32(const void* p) {
    uint32_t a;
    asm("{ .reg .u64 t; cvta.to.shared.u64 t, %1; cvt.u32.u64 %0, t; }"
        : "=r"(a) : "l"(p));
    return a;
}

// ---------- kernel ----------
__global__ void __launch_bounds__(THREADS, 4)
sph_harm_kernel(const float* __restrict__ coords, float* __restrict__ out, int n)
{
    extern __shared__ float sh[];           // TILE * SH_K floats
    const int base = blockIdx.x * TILE;
    const int t = threadIdx.x;
    const int lane = t & 31;                // point within tile
    const int w = t >> 5;                   // m residue (0..3)
    const int p = base + lane;

    if (p < n) {
        const float x = coords[3 * p + 0];
        const float y = coords[3 * p + 1];
        const float z = coords[3 * p + 2];

        const float r = sqrtf(x * x + y * y + z * z);
        float ct = z / r;
        ct = fminf(1.0f, fmaxf(-1.0f, ct));
        const float st = sqrtf(fmaxf(1.0f - ct * ct, 0.0f));
        const float st2 = st * st;
        const float st4 = st2 * st2;

        const float rho2 = x * x + y * y;
        float c1, s1;
        if (rho2 > 0.0f) {
            const float ir = rsqrtf(rho2);
            c1 = x * ir;
            s1 = y * ir;
        } else {
            c1 = 1.0f;
            s1 = 0.0f;
        }
        const float c2 = fmaf(c1, c1, -(s1 * s1));
        const float s2 = 2.0f * c1 * s1;
        const float c3 = fmaf(c2, c1, -(s2 * s1));
        const float s3 = fmaf(s2, c1, c2 * s1);
        const float c4 = fmaf(c2, c2, -(s2 * s2));
        const float s4 = 2.0f * c2 * s2;

        float* row = sh + lane * SH_K;

        if (w == 0) {
            mchain<0>(row, ct, st4, c4, s4, 1.0f, 1.0f, 0.0f);
        } else if (w == 1) {
            mchain<1>(row, ct, st4, c4, s4, -st, c1, s1);
        } else if (w == 2) {
            const float pmm = (3.0f * st) * st;                 // P_2^2
            mchain<2>(row, ct, st4, c4, s4, pmm, c2, s2);
        } else {
            const float pmm = ((-15.0f * st) * st) * st;        // P_3^3
            mchain<3>(row, ct, st4, c4, s4, pmm, c3, s3);
        }
    }

    // make STS visible to the async proxy, then sync the tile
    asm volatile("fence.proxy.async.shared::cta;" ::: "memory");
    __syncthreads();

    const int npts = min(TILE, n - base);
    if (npts <= 0) return;
    float* gbase = out + (size_t)base * SH_K;

    if (npts == TILE) {
        // full tile: single bulk TMA store (56448 B, 16B-aligned both sides).
        // wait only for the SMEM READ side to complete — GMEM writes drain
        // after CTA retirement; kernel completion still orders them.
        if (t == 0) {
            const uint32_t saddr = smem_u32(sh);
            asm volatile(
                "cp.async.bulk.global.shared::cta.bulk_group [%0], [%1], %2;"
                :: "l"(gbase), "r"(saddr), "r"((uint32_t)SMEM_BYTES)
                : "memory");
            asm volatile("cp.async.bulk.commit_group;" ::: "memory");
            asm volatile("cp.async.bulk.wait_group.read 0;" ::: "memory");
        }
    } else {
        // partial tail tile: scalar coalesced fallback
        const int total = npts * SH_K;
        for (int i = t; i < total; i += THREADS) {
            gbase[i] = sh[i];
        }
    }
}

extern "C" void kernel_launch(void* const* d_in, const int* in_sizes, int n_in,
                              void* d_out, int out_size) {
    const float* coords = (const float*)d_in[0];
    float* out = (float*)d_out;
    const int n = in_sizes[0] / 3;

    cudaFuncSetAttribute(sph_harm_kernel,
                         cudaFuncAttributeMaxDynamicSharedMemorySize, SMEM_BYTES);
    cudaFuncSetAttribute(sph_harm_kernel,
                         cudaFuncAttributePreferredSharedMemoryCarveout, 100);

    const int blocks = (n + TILE - 1) / TILE;
    sph_harm_kernel<<<blocks, THREADS, SMEM_BYTES>>>(coords, out, n);
}